// round 2
// baseline (speedup 1.0000x reference)
#include <cuda_runtime.h>
#include <math_constants.h>

#define B 64
#define T 2048
#define EMB 512
#define ATT 128
#define NF 32
#define KW 31
#define PADW 15
#define TB 64

// scratch: decoder query projection [B, ATT]
__device__ float g_q[B * ATT];

typedef unsigned long long u64;

__device__ __forceinline__ u64 pack2(float lo, float hi) {
    u64 r; asm("mov.b64 %0, {%1, %2};" : "=l"(r) : "f"(lo), "f"(hi)); return r;
}
__device__ __forceinline__ void unpack2(u64 v, float& lo, float& hi) {
    asm("mov.b64 {%0, %1}, %2;" : "=f"(lo), "=f"(hi) : "l"(v));
}
__device__ __forceinline__ u64 add2(u64 a, u64 b) {
    u64 r; asm("add.rn.f32x2 %0, %1, %2;" : "=l"(r) : "l"(a), "l"(b)); return r;
}
__device__ __forceinline__ void fma2(u64& d, u64 a, u64 b) {
    asm("fma.rn.f32x2 %0, %1, %2, %0;" : "+l"(d) : "l"(a), "l"(b));
}
__device__ __forceinline__ float tanh_apx(float x) {
    float r; asm("tanh.approx.f32 %0, %1;" : "=f"(r) : "f"(x)); return r;
}

// ---------------------------------------------------------------------------
// Kernel 1: q[b,a] = sum_h hidden[b,h] * W_dec[a,h]; also zero context region
// grid: (B), block: 256
// ---------------------------------------------------------------------------
__global__ void prep_kernel(const float* __restrict__ HID,
                            const float* __restrict__ WDEC,
                            float* __restrict__ OUT_CTX) {
    const int b = blockIdx.x;
    const int tid = threadIdx.x;
    const int w = tid >> 5, lane = tid & 31;

    // zero context output region: block b owns OUT_CTX[b*512 .. b*512+511]
    OUT_CTX[b * EMB + tid] = 0.f;
    OUT_CTX[b * EMB + 256 + tid] = 0.f;

    const float* __restrict__ h = HID + b * 1024;
    for (int a = w; a < ATT; a += 8) {
        const float* __restrict__ wd = WDEC + a * 1024;
        float acc = 0.f;
        #pragma unroll 8
        for (int hh = lane; hh < 1024; hh += 32)
            acc += h[hh] * wd[hh];
        #pragma unroll
        for (int s = 16; s; s >>= 1)
            acc += __shfl_xor_sync(0xffffffffu, acc, s);
        if (lane == 0) g_q[b * ATT + a] = acc;
    }
}

// ---------------------------------------------------------------------------
// Kernel 2: energies[b,t] = W_e . tanh(q[b] + proj(conv(cum))[b,t] + MA[b,t])
// masked -> -inf. grid: (T/TB, B), block: 128 (4 warps)
// ---------------------------------------------------------------------------
__global__ void energies_kernel(const float* __restrict__ MA,
                                const float* __restrict__ CUM,
                                const int* __restrict__ MASK,
                                const float* __restrict__ WCONV,
                                const float* __restrict__ WLOC,
                                const float* __restrict__ WE,
                                float* __restrict__ EOUT) {
    __shared__ float s_loc[TB][NF];            // loc[t][c]
    __shared__ float s_wloc[NF][ATT];          // W_loc transposed: [c][a]
    __shared__ float s_wconv[2][KW][NF];       // W_conv transposed: [i][k][c]
    __shared__ float s_cum[2][TB + 2 * PADW];  // halo tile

    const int b = blockIdx.y;
    const int t0 = blockIdx.x * TB;
    const int tid = threadIdx.x;

    // load W_loc [a][c] -> s_wloc[c][a], destination-linear (conflict-free STS)
    for (int idx = tid; idx < NF * ATT; idx += 128) {
        int c = idx >> 7, a = idx & 127;
        s_wloc[c][a] = __ldg(&WLOC[a * NF + c]);
    }
    // load W_conv [(c*2+i)*31+k] -> s_wconv[i][k][c]
    for (int idx = tid; idx < NF * 2 * KW; idx += 128) {
        int c = idx / 62, r = idx % 62;
        int i = r / KW, k = r % KW;
        s_wconv[i][k][c] = __ldg(&WCONV[idx]);
    }
    // cum halo tile
    for (int j = tid; j < 2 * (TB + 2 * PADW); j += 128) {
        int i = j / (TB + 2 * PADW);
        int jj = j % (TB + 2 * PADW);
        int tg = t0 + jj - PADW;
        s_cum[i][jj] = (tg >= 0 && tg < T) ? CUM[(b * 2 + i) * T + tg] : 0.f;
    }
    __syncthreads();

    // stage 1: conv1d -> s_loc[t][c]
    for (int idx = tid; idx < NF * TB; idx += 128) {
        int c = idx & 31, t = idx >> 5;
        float acc = 0.f;
        #pragma unroll
        for (int i = 0; i < 2; i++)
            #pragma unroll
            for (int k = 0; k < KW; k++)
                acc += s_wconv[i][k][c] * s_cum[i][t + k];
        s_loc[t][c] = acc;
    }
    __syncthreads();

    // stage 2: per (t): v[a] = q[a] + MA[a] + sum_c loc[c]*Wloc[c][a]; e = We.tanh(v)
    const int w = tid >> 5, lane = tid & 31;
    const float4 q4 = *((const float4*)(g_q + b * ATT) + lane);
    const float4 we4 = *((const float4*)WE + lane);
    const u64 q01 = pack2(q4.x, q4.y);
    const u64 q23 = pack2(q4.z, q4.w);
    const float4* __restrict__ MA4 = (const float4*)MA;

    for (int tt = w; tt < TB; tt += 4) {
        const int t = t0 + tt;
        const float4 m4 = MA4[((size_t)(b * T) + t) * (ATT / 4) + lane];
        u64 v01 = add2(q01, pack2(m4.x, m4.y));
        u64 v23 = add2(q23, pack2(m4.z, m4.w));
        #pragma unroll
        for (int c = 0; c < NF; c++) {
            float lc = s_loc[tt][c];                    // broadcast
            u64 lc2 = pack2(lc, lc);
            float4 wl = *((const float4*)(&s_wloc[c][0]) + lane);  // LDS.128
            fma2(v01, lc2, pack2(wl.x, wl.y));
            fma2(v23, lc2, pack2(wl.z, wl.w));
        }
        float a0, a1, a2, a3;
        unpack2(v01, a0, a1);
        unpack2(v23, a2, a3);
        float e = we4.x * tanh_apx(a0) + we4.y * tanh_apx(a1)
                + we4.z * tanh_apx(a2) + we4.w * tanh_apx(a3);
        #pragma unroll
        for (int s = 16; s; s >>= 1)
            e += __shfl_xor_sync(0xffffffffu, e, s);
        if (lane == 0) {
            EOUT[b * T + t] = (MASK[b * T + t] != 0) ? -CUDART_INF_F : e;
        }
    }
}

// ---------------------------------------------------------------------------
// Kernel 3: in-place masked softmax over T per batch row
// grid: (B), block: 256, 8 elems/thread
// ---------------------------------------------------------------------------
__global__ void softmax_kernel(float* __restrict__ W) {
    const int b = blockIdx.x;
    const int tid = threadIdx.x;
    const int w = tid >> 5, lane = tid & 31;
    __shared__ float red[8];
    __shared__ float bc;

    float* __restrict__ row = W + b * T;
    float vals[8];
    float mx = -CUDART_INF_F;
    #pragma unroll
    for (int j = 0; j < 8; j++) {
        vals[j] = row[tid + j * 256];
        mx = fmaxf(mx, vals[j]);
    }
    #pragma unroll
    for (int s = 16; s; s >>= 1) mx = fmaxf(mx, __shfl_xor_sync(0xffffffffu, mx, s));
    if (lane == 0) red[w] = mx;
    __syncthreads();
    if (tid == 0) {
        float m = red[0];
        #pragma unroll
        for (int i = 1; i < 8; i++) m = fmaxf(m, red[i]);
        bc = m;
    }
    __syncthreads();
    mx = bc;

    float sum = 0.f;
    #pragma unroll
    for (int j = 0; j < 8; j++) {
        vals[j] = __expf(vals[j] - mx);   // exp(-inf) = 0 for masked
        sum += vals[j];
    }
    #pragma unroll
    for (int s = 16; s; s >>= 1) sum += __shfl_xor_sync(0xffffffffu, sum, s);
    if (lane == 0) red[w] = sum;
    __syncthreads();
    if (tid == 0) {
        float m = 0.f;
        #pragma unroll
        for (int i = 0; i < 8; i++) m += red[i];
        bc = 1.f / m;
    }
    __syncthreads();
    const float inv = bc;
    #pragma unroll
    for (int j = 0; j < 8; j++)
        row[tid + j * 256] = vals[j] * inv;
}

// ---------------------------------------------------------------------------
// Kernel 4: context[b,d] = sum_t w[b,t] * memory[b,t,d]   (HBM-bound, 268MB)
// grid: (16 t-segments, B), block: 128 threads (each owns float4 -> 512 dims)
// ---------------------------------------------------------------------------
__global__ void context_kernel(const float* __restrict__ MEM,
                               const float* __restrict__ W,
                               float* __restrict__ CTX) {
    const int b = blockIdx.y;
    const int seg = blockIdx.x;
    const int tid = threadIdx.x;
    const int TSEG = T / 16;  // 128
    const int tbase = seg * TSEG;

    __shared__ float s_w[TSEG];
    if (tid < TSEG) s_w[tid] = W[b * T + tbase + tid];
    __syncthreads();

    const float4* __restrict__ M4 =
        (const float4*)MEM + ((size_t)b * T + tbase) * (EMB / 4);
    float4 acc = make_float4(0.f, 0.f, 0.f, 0.f);
    #pragma unroll 4
    for (int t = 0; t < TSEG; t++) {
        float4 m = M4[(size_t)t * (EMB / 4) + tid];
        float wt = s_w[t];
        acc.x += wt * m.x;
        acc.y += wt * m.y;
        acc.z += wt * m.z;
        acc.w += wt * m.w;
    }
    float* dst = CTX + b * EMB + tid * 4;
    atomicAdd(dst + 0, acc.x);
    atomicAdd(dst + 1, acc.y);
    atomicAdd(dst + 2, acc.z);
    atomicAdd(dst + 3, acc.w);
}

// ---------------------------------------------------------------------------
extern "C" void kernel_launch(void* const* d_in, const int* in_sizes, int n_in,
                              void* d_out, int out_size) {
    const float* hid   = (const float*)d_in[0];         // [B, 1024]
    const float* mem   = (const float*)d_in[1];         // [B, T, 512]
    const float* ma    = (const float*)d_in[2];         // [B, T, 128]
    const float* cum   = (const float*)d_in[3];         // [B, 2, T]
    const int*   mask  = (const int*)d_in[4];           // [B, T] bool -> int32
    const float* wdec  = (const float*)d_in[5];         // [128, 1024]
    const float* wconv = (const float*)d_in[6];         // [32, 2, 31]
    const float* wloc  = (const float*)d_in[7];         // [128, 32]
    const float* we    = (const float*)d_in[8];         // [1, 128]

    float* out_ctx = (float*)d_out;                  // [B, 512]
    float* out_w   = (float*)d_out + B * EMB;        // [B, T]

    prep_kernel<<<B, 256>>>(hid, wdec, out_ctx);
    dim3 ge(T / TB, B);
    energies_kernel<<<ge, 128>>>(ma, cum, mask, wconv, wloc, we, out_w);
    softmax_kernel<<<B, 256>>>(out_w);
    dim3 gc(16, B);
    context_kernel<<<gc, 128>>>(mem, out_w, out_ctx);
}

// round 3
// speedup vs baseline: 2.1139x; 2.1139x over previous
#include <cuda_runtime.h>
#include <math_constants.h>

#define B 64
#define T 2048
#define EMB 512
#define ATT 128
#define NF 32
#define KW 31
#define PADW 15
#define TB 64

// scratch: decoder query projection [B, ATT]
__device__ float g_q[B * ATT];

typedef unsigned long long u64;
typedef unsigned int u32;

__device__ __forceinline__ u64 pack2(float lo, float hi) {
    u64 r; asm("mov.b64 %0, {%1, %2};" : "=l"(r) : "f"(lo), "f"(hi)); return r;
}
__device__ __forceinline__ void unpack2(u64 v, float& lo, float& hi) {
    asm("mov.b64 {%0, %1}, %2;" : "=f"(lo), "=f"(hi) : "l"(v));
}
__device__ __forceinline__ u64 add2(u64 a, u64 b) {
    u64 r; asm("add.rn.f32x2 %0, %1, %2;" : "=l"(r) : "l"(a), "l"(b)); return r;
}
__device__ __forceinline__ void fma2(u64& d, u64 a, u64 b) {
    asm("fma.rn.f32x2 %0, %1, %2, %0;" : "+l"(d) : "l"(a), "l"(b));
}
__device__ __forceinline__ float tanh_apx(float x) {
    float r; asm("tanh.approx.f32 %0, %1;" : "=f"(r) : "f"(x)); return r;
}
__device__ __forceinline__ u32 sh_addr(const void* p) {
    return (u32)__cvta_generic_to_shared(p);
}
// one LDS.128 delivering two u64 halves of a W_loc quad
__device__ __forceinline__ void lds_v2u64(u64& a, u64& b, const void* p) {
    asm("ld.shared.v2.u64 {%0, %1}, [%2];" : "=l"(a), "=l"(b) : "r"(sh_addr(p)));
}
// broadcast 8B shared load
__device__ __forceinline__ u64 lds_u64(const void* p) {
    u64 r; asm("ld.shared.u64 %0, [%1];" : "=l"(r) : "r"(sh_addr(p))); return r;
}

// ---------------------------------------------------------------------------
// Kernel 1: q[b,a] = sum_h hidden[b,h] * W_dec[a,h]; also zero context region
// grid: (B), block: 256 (8 warps); warp owns rows a = w, w+8, ...
// hidden chunk preloaded to registers once, reused for 16 rows.
// ---------------------------------------------------------------------------
__global__ void prep_kernel(const float* __restrict__ HID,
                            const float* __restrict__ WDEC,
                            float* __restrict__ OUT_CTX) {
    const int b = blockIdx.x;
    const int tid = threadIdx.x;
    const int w = tid >> 5, lane = tid & 31;

    OUT_CTX[b * EMB + tid] = 0.f;
    OUT_CTX[b * EMB + 256 + tid] = 0.f;

    const float4* __restrict__ H4 = (const float4*)(HID + b * 1024);
    float4 h4[8];
    #pragma unroll
    for (int j = 0; j < 8; j++) h4[j] = H4[j * 32 + lane];

    const float4* __restrict__ WD4 = (const float4*)WDEC;
    for (int a = w; a < ATT; a += 8) {
        const float4* __restrict__ wd = WD4 + a * 256;
        float acc = 0.f;
        #pragma unroll
        for (int j = 0; j < 8; j++) {
            float4 v = wd[j * 32 + lane];
            acc += h4[j].x * v.x + h4[j].y * v.y + h4[j].z * v.z + h4[j].w * v.w;
        }
        #pragma unroll
        for (int s = 16; s; s >>= 1)
            acc += __shfl_xor_sync(0xffffffffu, acc, s);
        if (lane == 0) g_q[b * ATT + a] = acc;
    }
}

// ---------------------------------------------------------------------------
// Kernel 2: energies[b,t] = W_e . tanh(q[b] + proj(conv(cum))[b,t] + MA[b,t])
// grid: (T/TB, B), block: 128 (4 warps). Warp w owns t in [w*16, w*16+16).
// ---------------------------------------------------------------------------
__global__ void __launch_bounds__(128)
energies_kernel(const float* __restrict__ MA,
                const float* __restrict__ CUM,
                const int* __restrict__ MASK,
                const float* __restrict__ WCONV,
                const float* __restrict__ WLOC,
                const float* __restrict__ WE,
                float* __restrict__ EOUT) {
    __shared__ float  s_wloc[NF][ATT];            // [c][a]
    __shared__ float2 s_loc2[TB][NF];             // loc duplicated (v,v)
    __shared__ float2 s_cum2[TB + 2 * PADW];      // channel-interleaved cum
    __shared__ float2 s_wconv2[KW][NF];           // (W[c,0,k], W[c,1,k])

    const int b = blockIdx.y;
    const int t0 = blockIdx.x * TB;
    const int tid = threadIdx.x;
    const int w = tid >> 5, lane = tid & 31;

    for (int idx = tid; idx < NF * ATT; idx += 128) {
        int c = idx >> 7, a = idx & 127;
        s_wloc[c][a] = WLOC[a * NF + c];
    }
    for (int idx = tid; idx < KW * NF; idx += 128) {
        int k = idx >> 5, c = idx & 31;
        s_wconv2[k][c] = make_float2(WCONV[(c * 2 + 0) * KW + k],
                                     WCONV[(c * 2 + 1) * KW + k]);
    }
    for (int j = tid; j < TB + 2 * PADW; j += 128) {
        int tg = t0 + j - PADW;
        float a0 = 0.f, a1 = 0.f;
        if (tg >= 0 && tg < T) {
            a0 = CUM[(b * 2 + 0) * T + tg];
            a1 = CUM[(b * 2 + 1) * T + tg];
        }
        s_cum2[j] = make_float2(a0, a1);
    }
    __syncthreads();

    // --- stage 1: conv1d. lane = channel c, warp covers 16 t values.
    {
        u64 wk[KW];
        #pragma unroll
        for (int k = 0; k < KW; k++)
            wk[k] = lds_u64(&s_wconv2[k][lane]);
        const int tbase = w * 16;
        #pragma unroll 2
        for (int tt = 0; tt < 16; tt++) {
            const int t = tbase + tt;
            u64 acc = 0ull;  // (0.f, 0.f)
            #pragma unroll
            for (int k = 0; k < KW; k++)
                fma2(acc, wk[k], lds_u64(&s_cum2[t + k]));
            float lo, hi; unpack2(acc, lo, hi);
            float v = lo + hi;
            s_loc2[t][lane] = make_float2(v, v);
        }
    }
    __syncthreads();

    // --- stage 2: projection + tanh + energy dot, 8 t register-blocked.
    const float4 q4 = *((const float4*)(g_q + b * ATT) + lane);
    const float4 we4 = ((const float4*)WE)[lane];
    const u64 q01 = pack2(q4.x, q4.y);
    const u64 q23 = pack2(q4.z, q4.w);
    const float4* __restrict__ MA4 = (const float4*)MA;

    #pragma unroll
    for (int p = 0; p < 2; p++) {
        const int ts = w * 16 + p * 8;
        u64 v01[8], v23[8];
        int mj[8];
        #pragma unroll
        for (int j = 0; j < 8; j++) {
            const int t = t0 + ts + j;
            mj[j] = MASK[b * T + t];
            if (!mj[j]) {
                float4 m = MA4[((size_t)b * T + t) * (ATT / 4) + lane];
                v01[j] = add2(q01, pack2(m.x, m.y));
                v23[j] = add2(q23, pack2(m.z, m.w));
            } else {
                v01[j] = q01; v23[j] = q23;
            }
        }
        #pragma unroll 4
        for (int c = 0; c < NF; c++) {
            u64 w01, w23;
            lds_v2u64(w01, w23, &s_wloc[c][lane * 4]);
            #pragma unroll
            for (int j = 0; j < 8; j++) {
                u64 lc2 = lds_u64(&s_loc2[ts + j][c]);   // broadcast
                fma2(v01[j], lc2, w01);
                fma2(v23[j], lc2, w23);
            }
        }
        #pragma unroll
        for (int j = 0; j < 8; j++) {
            const int t = t0 + ts + j;
            if (mj[j]) {
                if (lane == 0) EOUT[b * T + t] = -CUDART_INF_F;
            } else {
                float a0, a1, a2, a3;
                unpack2(v01[j], a0, a1);
                unpack2(v23[j], a2, a3);
                float e = we4.x * tanh_apx(a0) + we4.y * tanh_apx(a1)
                        + we4.z * tanh_apx(a2) + we4.w * tanh_apx(a3);
                #pragma unroll
                for (int s = 16; s; s >>= 1)
                    e += __shfl_xor_sync(0xffffffffu, e, s);
                if (lane == 0) EOUT[b * T + t] = e;
            }
        }
    }
}

// ---------------------------------------------------------------------------
// Kernel 3: in-place masked softmax over T per batch row
// ---------------------------------------------------------------------------
__global__ void softmax_kernel(float* __restrict__ W) {
    const int b = blockIdx.x;
    const int tid = threadIdx.x;
    const int w = tid >> 5, lane = tid & 31;
    __shared__ float red[8];
    __shared__ float bc;

    float* __restrict__ row = W + b * T;
    float vals[8];
    float mx = -CUDART_INF_F;
    #pragma unroll
    for (int j = 0; j < 8; j++) {
        vals[j] = row[tid + j * 256];
        mx = fmaxf(mx, vals[j]);
    }
    #pragma unroll
    for (int s = 16; s; s >>= 1) mx = fmaxf(mx, __shfl_xor_sync(0xffffffffu, mx, s));
    if (lane == 0) red[w] = mx;
    __syncthreads();
    if (tid == 0) {
        float m = red[0];
        #pragma unroll
        for (int i = 1; i < 8; i++) m = fmaxf(m, red[i]);
        bc = m;
    }
    __syncthreads();
    mx = bc;

    float sum = 0.f;
    #pragma unroll
    for (int j = 0; j < 8; j++) {
        vals[j] = __expf(vals[j] - mx);   // exp(-inf) = exactly 0 for masked
        sum += vals[j];
    }
    #pragma unroll
    for (int s = 16; s; s >>= 1) sum += __shfl_xor_sync(0xffffffffu, sum, s);
    if (lane == 0) red[w] = sum;
    __syncthreads();
    if (tid == 0) {
        float m = 0.f;
        #pragma unroll
        for (int i = 0; i < 8; i++) m += red[i];
        bc = 1.f / m;
    }
    __syncthreads();
    const float inv = bc;
    #pragma unroll
    for (int j = 0; j < 8; j++)
        row[tid + j * 256] = vals[j] * inv;
}

// ---------------------------------------------------------------------------
// Kernel 4: context[b,d] = sum_t w[b,t] * memory[b,t,d]
// ~50% of weights are exactly 0 (masked) -> skip those rows entirely.
// grid: (32 t-segments, B), block 128, streaming loads.
// ---------------------------------------------------------------------------
__global__ void context_kernel(const float* __restrict__ MEM,
                               const float* __restrict__ W,
                               float* __restrict__ CTX) {
    const int TSEG = 64;
    const int b = blockIdx.y;
    const int tbase = blockIdx.x * TSEG;
    const int tid = threadIdx.x;

    __shared__ float s_w[TSEG];
    if (tid < TSEG) s_w[tid] = W[b * T + tbase + tid];
    __syncthreads();

    const float4* __restrict__ M4 =
        (const float4*)MEM + ((size_t)b * T + tbase) * (EMB / 4);
    float4 acc = make_float4(0.f, 0.f, 0.f, 0.f);
    #pragma unroll 8
    for (int t = 0; t < TSEG; t++) {
        float wt = s_w[t];
        if (wt != 0.f) {   // warp-uniform: skip masked rows (w exactly 0)
            float4 m = __ldcs(&M4[(size_t)t * (EMB / 4) + tid]);
            acc.x += wt * m.x;
            acc.y += wt * m.y;
            acc.z += wt * m.z;
            acc.w += wt * m.w;
        }
    }
    float* dst = CTX + b * EMB + tid * 4;
    atomicAdd(dst + 0, acc.x);
    atomicAdd(dst + 1, acc.y);
    atomicAdd(dst + 2, acc.z);
    atomicAdd(dst + 3, acc.w);
}

// ---------------------------------------------------------------------------
extern "C" void kernel_launch(void* const* d_in, const int* in_sizes, int n_in,
                              void* d_out, int out_size) {
    const float* hid   = (const float*)d_in[0];         // [B, 1024]
    const float* mem   = (const float*)d_in[1];         // [B, T, 512]
    const float* ma    = (const float*)d_in[2];         // [B, T, 128]
    const float* cum   = (const float*)d_in[3];         // [B, 2, T]
    const int*   mask  = (const int*)d_in[4];           // [B, T] bool -> int32
    const float* wdec  = (const float*)d_in[5];         // [128, 1024]
    const float* wconv = (const float*)d_in[6];         // [32, 2, 31]
    const float* wloc  = (const float*)d_in[7];         // [128, 32]
    const float* we    = (const float*)d_in[8];         // [1, 128]

    float* out_ctx = (float*)d_out;                  // [B, 512]
    float* out_w   = (float*)d_out + B * EMB;        // [B, T]

    prep_kernel<<<B, 256>>>(hid, wdec, out_ctx);
    dim3 ge(T / TB, B);
    energies_kernel<<<ge, 128>>>(ma, cum, mask, wconv, wloc, we, out_w);
    softmax_kernel<<<B, 256>>>(out_w);
    dim3 gc(32, B);
    context_kernel<<<gc, 128>>>(mem, out_w, out_ctx);
}

// round 4
// speedup vs baseline: 2.1210x; 1.0033x over previous
#include <cuda_runtime.h>
#include <math_constants.h>

#define B 64
#define T 2048
#define EMB 512
#define ATT 128
#define NF 32
#define KW 31
#define PADW 15
#define TB 64

// scratch
__device__ float g_q[B * ATT];    // decoder query projection
__device__ float g_sum[B];        // softmax denominators (atomic)

typedef unsigned long long u64;
typedef unsigned int u32;

__device__ __forceinline__ u64 pack2(float lo, float hi) {
    u64 r; asm("mov.b64 %0, {%1, %2};" : "=l"(r) : "f"(lo), "f"(hi)); return r;
}
__device__ __forceinline__ void unpack2(u64 v, float& lo, float& hi) {
    asm("mov.b64 {%0, %1}, %2;" : "=f"(lo), "=f"(hi) : "l"(v));
}
__device__ __forceinline__ u64 add2(u64 a, u64 b) {
    u64 r; asm("add.rn.f32x2 %0, %1, %2;" : "=l"(r) : "l"(a), "l"(b)); return r;
}
__device__ __forceinline__ void fma2(u64& d, u64 a, u64 b) {
    asm("fma.rn.f32x2 %0, %1, %2, %0;" : "+l"(d) : "l"(a), "l"(b));
}
__device__ __forceinline__ float tanh_apx(float x) {
    float r; asm("tanh.approx.f32 %0, %1;" : "=f"(r) : "f"(x)); return r;
}

// ---------------------------------------------------------------------------
// Kernel 1: q = hidden @ W_dec^T; zero context region; zero g_sum
// ---------------------------------------------------------------------------
__global__ void prep_kernel(const float* __restrict__ HID,
                            const float* __restrict__ WDEC,
                            float* __restrict__ OUT_CTX) {
    const int b = blockIdx.x;
    const int tid = threadIdx.x;
    const int w = tid >> 5, lane = tid & 31;

    OUT_CTX[b * EMB + tid] = 0.f;
    OUT_CTX[b * EMB + 256 + tid] = 0.f;
    if (tid == 0) g_sum[b] = 0.f;

    const float4* __restrict__ H4 = (const float4*)(HID + b * 1024);
    float4 h4[8];
    #pragma unroll
    for (int j = 0; j < 8; j++) h4[j] = H4[j * 32 + lane];

    const float4* __restrict__ WD4 = (const float4*)WDEC;
    for (int a = w; a < ATT; a += 8) {
        const float4* __restrict__ wd = WD4 + a * 256;
        float acc = 0.f;
        #pragma unroll
        for (int j = 0; j < 8; j++) {
            float4 v = wd[j * 32 + lane];
            acc += h4[j].x * v.x + h4[j].y * v.y + h4[j].z * v.z + h4[j].w * v.w;
        }
        #pragma unroll
        for (int s = 16; s; s >>= 1)
            acc += __shfl_xor_sync(0xffffffffu, acc, s);
        if (lane == 0) g_q[b * ATT + a] = acc;
    }
}

// ---------------------------------------------------------------------------
// Kernel 2: w'[b,t] = exp(W_e . tanh(q + proj(conv(cum)) + MA)); masked -> 0.
// Also atomically accumulates sum_t w' into g_sum[b].
// grid: (T/TB, B), block 128 (4 warps); warp owns 16 consecutive t.
// ---------------------------------------------------------------------------
__global__ void __launch_bounds__(128)
energies_kernel(const float* __restrict__ MA,
                const float* __restrict__ CUM,
                const int* __restrict__ MASK,
                const float* __restrict__ WCONV,
                const float* __restrict__ WLOC,
                const float* __restrict__ WE,
                float* __restrict__ WOUT) {
    __shared__ float  s_wloc[NF][ATT];                    // [c][a]
    __shared__ u64    s_locd[NF][TB + 2];                 // duplicated (v,v), stride 66
    __shared__ alignas(16) float2 s_cum2[TB + 2 * PADW + 2];
    __shared__ float2 s_wconv2[KW][NF];                   // (W[c,0,k], W[c,1,k])

    const int b = blockIdx.y;
    const int t0 = blockIdx.x * TB;
    const int tid = threadIdx.x;
    const int w = tid >> 5, lane = tid & 31;

    for (int idx = tid; idx < NF * ATT; idx += 128) {
        int c = idx >> 7, a = idx & 127;
        s_wloc[c][a] = WLOC[a * NF + c];
    }
    for (int idx = tid; idx < KW * NF; idx += 128) {
        int k = idx >> 5, c = idx & 31;
        s_wconv2[k][c] = make_float2(WCONV[(c * 2 + 0) * KW + k],
                                     WCONV[(c * 2 + 1) * KW + k]);
    }
    for (int j = tid; j < TB + 2 * PADW + 2; j += 128) {
        int tg = t0 + j - PADW;
        float a0 = 0.f, a1 = 0.f;
        if (tg >= 0 && tg < T) {
            a0 = CUM[(b * 2 + 0) * T + tg];
            a1 = CUM[(b * 2 + 1) * T + tg];
        }
        s_cum2[j] = make_float2(a0, a1);
    }
    __syncthreads();

    const int tl = w * 16;  // warp's local t-base (even)

    // --- stage 1: conv1d, lane = channel, t processed in pairs.
    // One broadcast LDS.128 per tap-pair serves both t and t+1.
    {
        u64 wk[KW];
        #pragma unroll
        for (int k = 0; k < KW; k++) {
            float2 wv = s_wconv2[k][lane];
            wk[k] = pack2(wv.x, wv.y);
        }
        #pragma unroll 2
        for (int u = 0; u < 8; u++) {
            const int tp = tl + 2 * u;   // even
            u64 a0 = 0ull, a1 = 0ull;
            #pragma unroll
            for (int m = 0; m < 16; m++) {
                float4 F = *(const float4*)&s_cum2[tp + 2 * m];  // 16B broadcast
                u64 flo = pack2(F.x, F.y);   // cum2[tp+2m]
                u64 fhi = pack2(F.z, F.w);   // cum2[tp+2m+1]
                fma2(a0, wk[2 * m], flo);                   // t: k=2m
                if (2 * m + 1 < KW) fma2(a0, wk[2 * m + 1], fhi);  // t: k=2m+1
                if (m > 0) fma2(a1, wk[2 * m - 1], flo);    // t+1: k=2m-1
                fma2(a1, wk[2 * m], fhi);                   // t+1: k=2m
            }
            float l0, h0, l1, h1;
            unpack2(a0, l0, h0);
            unpack2(a1, l1, h1);
            float v0 = l0 + h0, v1 = l1 + h1;
            s_locd[lane][tp]     = pack2(v0, v0);
            s_locd[lane][tp + 1] = pack2(v1, v1);
        }
    }
    __syncthreads();

    // --- stage 2: projection (16-t register blocked) + tanh + energy + exp.
    const float4 q4 = *((const float4*)(g_q + b * ATT) + lane);
    const float4 we4 = ((const float4*)WE)[lane];
    const u64 q01 = pack2(q4.x, q4.y);
    const u64 q23 = pack2(q4.z, q4.w);
    const float4* __restrict__ MA4 = (const float4*)MA;

    u64 v01[16], v23[16];
    int mj[16];
    #pragma unroll
    for (int j = 0; j < 16; j++) {
        const int t = t0 + tl + j;
        mj[j] = MASK[b * T + t];
        if (!mj[j]) {
            float4 m = MA4[((size_t)b * T + t) * (ATT / 4) + lane];
            v01[j] = add2(q01, pack2(m.x, m.y));
            v23[j] = add2(q23, pack2(m.z, m.w));
        } else {
            v01[j] = q01; v23[j] = q23;
        }
    }
    #pragma unroll 4
    for (int c = 0; c < NF; c++) {
        float4 wf = ((const float4*)s_wloc[c])[lane];   // LDS.128, lane-distinct
        u64 w01 = pack2(wf.x, wf.y);
        u64 w23 = pack2(wf.z, wf.w);
        #pragma unroll
        for (int r = 0; r < 8; r++) {
            ulonglong2 L = *(const ulonglong2*)&s_locd[c][tl + 2 * r]; // 16B broadcast
            fma2(v01[2 * r],     L.x, w01);
            fma2(v23[2 * r],     L.x, w23);
            fma2(v01[2 * r + 1], L.y, w01);
            fma2(v23[2 * r + 1], L.y, w23);
        }
    }

    float psum = 0.f;
    #pragma unroll
    for (int j = 0; j < 16; j++) {
        const int t = t0 + tl + j;
        if (mj[j]) {
            if (lane == 0) WOUT[b * T + t] = 0.f;
        } else {
            float a0, a1, a2, a3;
            unpack2(v01[j], a0, a1);
            unpack2(v23[j], a2, a3);
            float e = we4.x * tanh_apx(a0) + we4.y * tanh_apx(a1)
                    + we4.z * tanh_apx(a2) + we4.w * tanh_apx(a3);
            #pragma unroll
            for (int s = 16; s; s >>= 1)
                e += __shfl_xor_sync(0xffffffffu, e, s);
            // |e| <= sum|We| * 1 < ~3, exp safe without max subtraction
            float wexp = __expf(e);
            if (lane == 0) {
                WOUT[b * T + t] = wexp;
                psum += wexp;
            }
        }
    }
    if (lane == 0) atomicAdd(&g_sum[b], psum);
}

// ---------------------------------------------------------------------------
// Kernel 3: normalize weights in place + context = sum_t w[t]*memory[t,:]
// grid: (16, B), block 128. Skips rows with w' == 0 (masked).
// ---------------------------------------------------------------------------
__global__ void context_kernel(const float* __restrict__ MEM,
                               float* __restrict__ WROW,
                               float* __restrict__ CTX) {
    const int TSEG = 128;
    const int b = blockIdx.y;
    const int tbase = blockIdx.x * TSEG;
    const int tid = threadIdx.x;

    __shared__ float s_w[TSEG];
    s_w[tid] = WROW[b * T + tbase + tid];
    __syncthreads();

    const float inv = 1.f / g_sum[b];
    // write normalized weight (this block owns this t range exclusively)
    WROW[b * T + tbase + tid] = s_w[tid] * inv;

    const float4* __restrict__ M4 =
        (const float4*)MEM + ((size_t)b * T + tbase) * (EMB / 4);
    float4 acc = make_float4(0.f, 0.f, 0.f, 0.f);
    #pragma unroll 8
    for (int t = 0; t < TSEG; t++) {
        float wt = s_w[t];
        if (wt != 0.f) {   // warp-uniform skip of masked rows
            float4 m = __ldcs(&M4[(size_t)t * (EMB / 4) + tid]);
            acc.x += wt * m.x;
            acc.y += wt * m.y;
            acc.z += wt * m.z;
            acc.w += wt * m.w;
        }
    }
    float* dst = CTX + b * EMB + tid * 4;
    atomicAdd(dst + 0, acc.x * inv);
    atomicAdd(dst + 1, acc.y * inv);
    atomicAdd(dst + 2, acc.z * inv);
    atomicAdd(dst + 3, acc.w * inv);
}

// ---------------------------------------------------------------------------
extern "C" void kernel_launch(void* const* d_in, const int* in_sizes, int n_in,
                              void* d_out, int out_size) {
    const float* hid   = (const float*)d_in[0];         // [B, 1024]
    const float* mem   = (const float*)d_in[1];         // [B, T, 512]
    const float* ma    = (const float*)d_in[2];         // [B, T, 128]
    const float* cum   = (const float*)d_in[3];         // [B, 2, T]
    const int*   mask  = (const int*)d_in[4];           // [B, T] bool -> int32
    const float* wdec  = (const float*)d_in[5];         // [128, 1024]
    const float* wconv = (const float*)d_in[6];         // [32, 2, 31]
    const float* wloc  = (const float*)d_in[7];         // [128, 32]
    const float* we    = (const float*)d_in[8];         // [1, 128]

    float* out_ctx = (float*)d_out;                  // [B, 512]
    float* out_w   = (float*)d_out + B * EMB;        // [B, T]

    prep_kernel<<<B, 256>>>(hid, wdec, out_ctx);
    dim3 ge(T / TB, B);
    energies_kernel<<<ge, 128>>>(ma, cum, mask, wconv, wloc, we, out_w);
    dim3 gc(16, B);
    context_kernel<<<gc, 128>>>(mem, out_w, out_ctx);
}

// round 5
// speedup vs baseline: 3.0095x; 1.4189x over previous
#include <cuda_runtime.h>
#include <math_constants.h>

#define B 64
#define T 2048
#define EMB 512
#define ATT 128
#define NF 32
#define KW 31
#define PADW 15
#define TB 64

__device__ float g_q[B * ATT];
__device__ float g_sum[B];
__device__ float g_wlocT[NF * ATT];
__device__ float2 g_wconv2[KW * NF];

typedef unsigned long long u64;
typedef unsigned int u32;

__device__ __forceinline__ u64 pack2(float lo, float hi) {
    u64 r; asm("mov.b64 %0, {%1, %2};" : "=l"(r) : "f"(lo), "f"(hi)); return r;
}
__device__ __forceinline__ void unpack2(u64 v, float& lo, float& hi) {
    asm("mov.b64 {%0, %1}, %2;" : "=f"(lo), "=f"(hi) : "l"(v));
}
__device__ __forceinline__ u64 add2(u64 a, u64 b) {
    u64 r; asm("add.rn.f32x2 %0, %1, %2;" : "=l"(r) : "l"(a), "l"(b)); return r;
}
__device__ __forceinline__ void fma2(u64& d, u64 a, u64 b) {
    asm("fma.rn.f32x2 %0, %1, %2, %0;" : "+l"(d) : "l"(a), "l"(b));
}
__device__ __forceinline__ float tanh_apx(float x) {
    float r; asm("tanh.approx.f32 %0, %1;" : "=f"(r) : "f"(x)); return r;
}

// ---------------------------------------------------------------------------
__global__ void __launch_bounds__(256)
prep_kernel(const float* __restrict__ HID,
            const float* __restrict__ WDEC,
            const float* __restrict__ WLOC,
            const float* __restrict__ WCONV,
            float* __restrict__ OUT_CTX) {
    const int b = blockIdx.x;
    const int chunk = blockIdx.y;
    const int tid = threadIdx.x;
    const int w = tid >> 5, lane = tid & 31;

    if (chunk == 0) {
        OUT_CTX[b * EMB + tid] = 0.f;
        OUT_CTX[b * EMB + 256 + tid] = 0.f;
        if (tid == 0) g_sum[b] = 0.f;
    }
    if (b == 0 && chunk == 1) {
        for (int idx = tid; idx < NF * ATT; idx += 256) {
            int a = idx >> 5, c = idx & 31;
            g_wlocT[c * ATT + a] = WLOC[idx];
        }
        for (int idx = tid; idx < KW * NF; idx += 256) {
            int c = idx & 31, k = idx >> 5;
            g_wconv2[k * NF + c] = make_float2(WCONV[(c * 2 + 0) * KW + k],
                                               WCONV[(c * 2 + 1) * KW + k]);
        }
    }

    const float4* __restrict__ H4 = (const float4*)(HID + b * 1024);
    float4 h4[8];
    #pragma unroll
    for (int j = 0; j < 8; j++) h4[j] = H4[j * 32 + lane];

    const int a0 = chunk * 32 + w * 4;
    const float4* __restrict__ WD4 = (const float4*)WDEC;
    float acc0 = 0.f, acc1 = 0.f, acc2 = 0.f, acc3 = 0.f;
    #pragma unroll
    for (int j = 0; j < 8; j++) {
        float4 v0 = WD4[(a0 + 0) * 256 + j * 32 + lane];
        float4 v1 = WD4[(a0 + 1) * 256 + j * 32 + lane];
        float4 v2 = WD4[(a0 + 2) * 256 + j * 32 + lane];
        float4 v3 = WD4[(a0 + 3) * 256 + j * 32 + lane];
        acc0 += h4[j].x * v0.x + h4[j].y * v0.y + h4[j].z * v0.z + h4[j].w * v0.w;
        acc1 += h4[j].x * v1.x + h4[j].y * v1.y + h4[j].z * v1.z + h4[j].w * v1.w;
        acc2 += h4[j].x * v2.x + h4[j].y * v2.y + h4[j].z * v2.z + h4[j].w * v2.w;
        acc3 += h4[j].x * v3.x + h4[j].y * v3.y + h4[j].z * v3.z + h4[j].w * v3.w;
    }
    #pragma unroll
    for (int s = 16; s; s >>= 1) {
        acc0 += __shfl_xor_sync(0xffffffffu, acc0, s);
        acc1 += __shfl_xor_sync(0xffffffffu, acc1, s);
        acc2 += __shfl_xor_sync(0xffffffffu, acc2, s);
        acc3 += __shfl_xor_sync(0xffffffffu, acc3, s);
    }
    if (lane == 0) {
        g_q[b * ATT + a0 + 0] = acc0;
        g_q[b * ATT + a0 + 1] = acc1;
        g_q[b * ATT + a0 + 2] = acc2;
        g_q[b * ATT + a0 + 3] = acc3;
    }
}

// ---------------------------------------------------------------------------
__global__ void __launch_bounds__(128)
energies_kernel(const float* __restrict__ MA,
                const float* __restrict__ CUM,
                const int* __restrict__ MASK,
                const float* __restrict__ WE,
                float* __restrict__ WOUT) {
    __shared__ float s_wloc[NF][ATT];
    __shared__ u64   s_locd[NF][TB + 2];
    __shared__ alignas(16) float2 s_cum2[TB + 2 * PADW + 2];

    const int b = blockIdx.y;
    const int t0 = blockIdx.x * TB;
    const int tid = threadIdx.x;
    const int w = tid >> 5, lane = tid & 31;

    {
        const float4* __restrict__ src = (const float4*)g_wlocT;
        float4* dst = (float4*)s_wloc;
        #pragma unroll
        for (int j = 0; j < 8; j++) dst[tid + j * 128] = src[tid + j * 128];
    }
    for (int j = tid; j < TB + 2 * PADW + 2; j += 128) {
        int tg = t0 + j - PADW;
        float a0 = 0.f, a1 = 0.f;
        if (tg >= 0 && tg < T) {
            a0 = CUM[(b * 2 + 0) * T + tg];
            a1 = CUM[(b * 2 + 1) * T + tg];
        }
        s_cum2[j] = make_float2(a0, a1);
    }
    __syncthreads();

    const int tl = w * 16;

    {
        u64 wk[KW];
        #pragma unroll
        for (int k = 0; k < KW; k++) {
            float2 wv = __ldg(&g_wconv2[k * NF + lane]);
            wk[k] = pack2(wv.x, wv.y);
        }
        #pragma unroll 2
        for (int u = 0; u < 8; u++) {
            const int tp = tl + 2 * u;
            u64 a0 = 0ull, a1 = 0ull;
            #pragma unroll
            for (int m = 0; m < 16; m++) {
                float4 F = *(const float4*)&s_cum2[tp + 2 * m];
                u64 flo = pack2(F.x, F.y);
                u64 fhi = pack2(F.z, F.w);
                fma2(a0, wk[2 * m], flo);
                if (2 * m + 1 < KW) fma2(a0, wk[2 * m + 1], fhi);
                if (m > 0) fma2(a1, wk[2 * m - 1], flo);
                fma2(a1, wk[2 * m], fhi);
            }
            float l0, h0, l1, h1;
            unpack2(a0, l0, h0);
            unpack2(a1, l1, h1);
            float v0 = l0 + h0, v1 = l1 + h1;
            s_locd[lane][tp]     = pack2(v0, v0);
            s_locd[lane][tp + 1] = pack2(v1, v1);
        }
    }
    __syncthreads();

    const float4 q4 = *((const float4*)(g_q + b * ATT) + lane);
    const float4 we4 = ((const float4*)WE)[lane];
    const u64 q01 = pack2(q4.x, q4.y);
    const u64 q23 = pack2(q4.z, q4.w);
    const float4* __restrict__ MA4 = (const float4*)MA;

    float psum = 0.f;
    #pragma unroll
    for (int p = 0; p < 2; p++) {
        const int ts = tl + p * 8;

        int mv = 0;
        if (lane < 8) mv = MASK[b * T + t0 + ts + lane];
        const unsigned mb = __ballot_sync(0xffffffffu, mv != 0) & 0xffu;

        u64 v01[8], v23[8];
        #pragma unroll
        for (int j = 0; j < 8; j++) {
            if (!((mb >> j) & 1u)) {
                const int t = t0 + ts + j;
                float4 m = MA4[((size_t)b * T + t) * (ATT / 4) + lane];
                v01[j] = add2(q01, pack2(m.x, m.y));
                v23[j] = add2(q23, pack2(m.z, m.w));
            } else {
                v01[j] = q01; v23[j] = q23;
            }
        }
        #pragma unroll 4
        for (int c = 0; c < NF; c++) {
            float4 wf = ((const float4*)s_wloc[c])[lane];
            u64 w01 = pack2(wf.x, wf.y);
            u64 w23 = pack2(wf.z, wf.w);
            #pragma unroll
            for (int r = 0; r < 4; r++) {
                ulonglong2 L = *(const ulonglong2*)&s_locd[c][ts + 2 * r];
                fma2(v01[2 * r],     L.x, w01);
                fma2(v23[2 * r],     L.x, w23);
                fma2(v01[2 * r + 1], L.y, w01);
                fma2(v23[2 * r + 1], L.y, w23);
            }
        }

        float myw = 0.f;
        #pragma unroll
        for (int j = 0; j < 8; j++) {
            if (!((mb >> j) & 1u)) {
                float a0, a1, a2, a3;
                unpack2(v01[j], a0, a1);
                unpack2(v23[j], a2, a3);
                float e = we4.x * tanh_apx(a0) + we4.y * tanh_apx(a1)
                        + we4.z * tanh_apx(a2) + we4.w * tanh_apx(a3);
                #pragma unroll
                for (int s = 16; s; s >>= 1)
                    e += __shfl_xor_sync(0xffffffffu, e, s);
                float wexp = __expf(e);
                if (lane == j) myw = wexp;
                psum += wexp;
            }
        }
        if (lane < 8) WOUT[b * T + t0 + ts + lane] = myw;
    }
    if (lane == 0) atomicAdd(&g_sum[b], psum * (1.f / 32.f) * 32.f == psum ? psum : psum);
}

// ---------------------------------------------------------------------------
__global__ void context_kernel(const float* __restrict__ MEM,
                               float* __restrict__ WROW,
                               float* __restrict__ CTX) {
    const int TSEG = 128;
    const int b = blockIdx.y;
    const int tbase = blockIdx.x * TSEG;
    const int tid = threadIdx.x;

    __shared__ float s_w[TSEG];
    s_w[tid] = WROW[b * T + tbase + tid];
    __syncthreads();

    const float inv = 1.f / g_sum[b];
    WROW[b * T + tbase + tid] = s_w[tid] * inv;

    const float4* __restrict__ M4 =
        (const float4*)MEM + ((size_t)b * T + tbase) * (EMB / 4);
    float4 acc = make_float4(0.f, 0.f, 0.f, 0.f);
    #pragma unroll 8
    for (int t = 0; t < TSEG; t++) {
        float wt = s_w[t];
        if (wt != 0.f) {
            float4 m = __ldcs(&M4[(size_t)t * (EMB / 4) + tid]);
            acc.x += wt * m.x;
            acc.y += wt * m.y;
            acc.z += wt * m.z;
            acc.w += wt * m.w;
        }
    }
    float* dst = CTX + b * EMB + tid * 4;
    atomicAdd(dst + 0, acc.x * inv);
    atomicAdd(dst + 1, acc.y * inv);
    atomicAdd(dst + 2, acc.z * inv);
    atomicAdd(dst + 3, acc.w * inv);
}

// ---------------------------------------------------------------------------
extern "C" void kernel_launch(void* const* d_in, const int* in_sizes, int n_in,
                              void* d_out, int out_size) {
    const float* hid   = (const float*)d_in[0];
    const float* mem   = (const float*)d_in[1];
    const float* ma    = (const float*)d_in[2];
    const float* cum   = (const float*)d_in[3];
    const int*   mask  = (const int*)d_in[4];
    const float* wdec  = (const float*)d_in[5];
    const float* wconv = (const float*)d_in[6];
    const float* wloc  = (const float*)d_in[7];
    const float* we    = (const float*)d_in[8];

    float* out_ctx = (float*)d_out;
    float* out_w   = (float*)d_out + B * EMB;

    dim3 gp(B, 4);
    prep_kernel<<<gp, 256>>>(hid, wdec, wloc, wconv, out_ctx);
    dim3 ge(T / TB, B);
    energies_kernel<<<ge, 128>>>(ma, cum, mask, we, out_w);
    dim3 gc(16, B);
    context_kernel<<<gc, 128>>>(mem, out_w, out_ctx);
}